// round 12
// baseline (speedup 1.0000x reference)
#include <cuda_runtime.h>
#include <cuda_fp16.h>

#define TAB 2048
#define FULLMASK 0xffffffffu
#define EB 1184            // edge blocks per filter
typedef unsigned long long ull;

__device__ __half g_htabh[2][TAB * 128];   // fp16 length->h tables
__device__ float4 g_einv[1000000];         // per-edge SO3 invariants
__device__ float2 g_etf[1000000];          // per-edge (tf, bitcast ti)
__device__ float  g_wpk[2][2][4096];       // [filt][hi/lo][ks*1024 + n*8 + tk*2 + p]

__device__ __forceinline__ float silu_f(float x) {
    float h = 0.5f * x, t;
    asm("tanh.approx.f32 %0, %1;" : "=f"(t) : "f"(h));
    return fmaf(h, t, h);
}
__device__ __forceinline__ float silu_acc(float x) { return __fdividef(x, 1.0f + __expf(-x)); }

__device__ __forceinline__ ull dup2(float x) {
    ull r; unsigned u = __float_as_uint(x);
    asm("mov.b64 %0, {%1,%1};" : "=l"(r) : "r"(u)); return r;
}
__device__ __forceinline__ void fma2(ull &d, ull a, ull b) {
    asm("fma.rn.f32x2 %0, %1, %2, %0;" : "+l"(d) : "l"(a), "l"(b));
}
__device__ __forceinline__ void unpack2(ull v, float &lo, float &hi) {
    unsigned a, b; asm("mov.b64 {%0,%1}, %2;" : "=r"(a), "=r"(b) : "l"(v));
    lo = __uint_as_float(a); hi = __uint_as_float(b);
}
__device__ __forceinline__ unsigned tf32_rna(float x) {
    unsigned r; asm("cvt.rna.tf32.f32 %0, %1;" : "=r"(r) : "f"(x)); return r;
}
__device__ __forceinline__ void mma_tf32(float c[4],
    unsigned a0, unsigned a1, unsigned a2, unsigned a3, unsigned b0, unsigned b1)
{
    asm volatile(
        "mma.sync.aligned.m16n8k8.row.col.f32.tf32.tf32.f32 "
        "{%0,%1,%2,%3}, {%4,%5,%6,%7}, {%8,%9}, {%0,%1,%2,%3};"
        : "+f"(c[0]), "+f"(c[1]), "+f"(c[2]), "+f"(c[3])
        : "r"(a0), "r"(a1), "r"(a2), "r"(a3), "r"(b0), "r"(b1));
}

// ===========================================================================
// Setup kernel (short): [0,16) weight pack, [16,144) tables, [144,144+PB) prep
// ===========================================================================
__global__ void __launch_bounds__(256) setup_kernel(
    const float* __restrict__ evf,
    const int* __restrict__ senders, const int* __restrict__ receivers,
    const float* __restrict__ lengths,
    const float* __restrict__ fi_rbf_w1, const float* __restrict__ fi_rbf_b1,
    const float* __restrict__ fi_rbf_w2, const float* __restrict__ fi_rbf_b2,
    const float* __restrict__ fe_rbf_w1, const float* __restrict__ fe_rbf_b1,
    const float* __restrict__ fe_rbf_w2, const float* __restrict__ fe_rbf_b2,
    const float* __restrict__ fi_ev_w2, const float* __restrict__ fe_ev_w2,
    int E)
{
    int bid = blockIdx.x;
    int tid = threadIdx.x;

    if (bid < 16) {
        int g = bid * 256 + tid;            // 4096 = 2 filt * 2048
        int filt = g >> 11;
        int j = g & 2047;
        int ks = j >> 9;
        int rem = j & 511;
        int n = rem >> 2;
        int tk = rem & 3;
        const float* w2 = filt ? fe_ev_w2 : fi_ev_w2;
        int k0 = ks * 8 + tk;
        float wa = __ldg(&w2[k0 * 128 + n]);
        float wb = __ldg(&w2[(k0 + 4) * 128 + n]);
        float ha = __uint_as_float(tf32_rna(wa));
        float hb = __uint_as_float(tf32_rna(wb));
        int idx = ks * 1024 + n * 8 + tk * 2;
        g_wpk[filt][0][idx]     = ha;
        g_wpk[filt][0][idx + 1] = hb;
        g_wpk[filt][1][idx]     = __uint_as_float(tf32_rna(wa - ha));
        g_wpk[filt][1][idx + 1] = __uint_as_float(tf32_rna(wb - hb));
        return;
    }

    if (bid < 144) {
        int tb = bid - 16;
        int filt = tb >> 6;
        const float* w1 = filt ? fe_rbf_w1 : fi_rbf_w1;
        const float* b1 = filt ? fe_rbf_b1 : fi_rbf_b1;
        const float* w2 = filt ? fe_rbf_w2 : fi_rbf_w2;
        const float* b2 = filt ? fe_rbf_b2 : fi_rbf_b2;
        __shared__ float h1s[128];
        int f = tid & 127;
        float w1col[32];
#pragma unroll
        for (int k = 0; k < 32; k++) w1col[k] = __ldg(&w1[k * 128 + f]);
        float b1f = __ldg(&b1[f]), b2f = __ldg(&b2[f]);
        const float step  = 5.0f / 31.0f;
        const float gamma = 0.5f / (step * step);
        const float dx    = 5.0f / (float)(TAB - 1);
        int r0 = (tb & 63) * 32;
        for (int rr = 0; rr < 32; rr++) {
            int row = r0 + rr;
            float x = (float)row * dx;
            float a1 = b1f;
#pragma unroll
            for (int k = 0; k < 32; k++) {
                float d = x - (float)k * step;
                a1 = fmaf(__expf(-gamma * d * d), w1col[k], a1);
            }
            h1s[f] = silu_acc(a1);
            __syncthreads();
            float a2 = b2f;
#pragma unroll 16
            for (int k = 0; k < 128; k++) a2 = fmaf(h1s[k], __ldg(&w2[k * 128 + f]), a2);
            g_htabh[filt][(size_t)row * 128 + f] = __float2half_rn(silu_acc(a2));
            __syncthreads();
        }
        return;
    }

    // -------- edge prep --------
    int e = (bid - 144) * 256 + tid;
    if (e >= E) return;
    const float tscale = (float)(TAB - 1) / 5.0f;
    int sN = __ldg(senders + e), rN = __ldg(receivers + e);
    const float4* As = reinterpret_cast<const float4*>(evf) + (size_t)sN * 4;
    const float4* Ar = reinterpret_cast<const float4*>(evf) + (size_t)rN * 4;
    float4 a, b; float dx, dy, dz, dw;
    float i0, i1, i2, i3;
    a = __ldg(As);     b = __ldg(Ar);     dx = a.x-b.x; dy = a.y-b.y; dz = a.z-b.z; dw = a.w-b.w;
    i0 = dx*dx; i1 = dy*dy + dz*dz + dw*dw;
    a = __ldg(As + 1); b = __ldg(Ar + 1); dx = a.x-b.x; dy = a.y-b.y; dz = a.z-b.z; dw = a.w-b.w;
    i2 = dx*dx + dy*dy + dz*dz + dw*dw;
    a = __ldg(As + 2); b = __ldg(Ar + 2); dx = a.x-b.x; dy = a.y-b.y; dz = a.z-b.z; dw = a.w-b.w;
    i2 += dx*dx; i3 = dy*dy + dz*dz + dw*dw;
    a = __ldg(As + 3); b = __ldg(Ar + 3); dx = a.x-b.x; dy = a.y-b.y; dz = a.z-b.z; dw = a.w-b.w;
    i3 += dx*dx + dy*dy + dz*dz + dw*dw;
    float xf = __ldg(lengths + e) * tscale;
    int ti = (int)xf;
    if (ti < 0) ti = 0; if (ti > TAB - 2) ti = TAB - 2;
    g_einv[e] = make_float4(i0, i1, i2, i3);
    g_etf[e]  = make_float2(xf - (float)ti, __int_as_float(ti));
}

// ===========================================================================
// Main fused kernel (128 threads/block):
//   blocks [0, NB)            : node update (independent work, overlaps)
//   blocks [NB, NB + 2*EB)    : edge filter nets (filt = (bid-NB)&1)
// Edge: block = 16 edges/pass; 4 warps each own 32 output features; hi-weights
// live in registers, layer-1/staging shared across warps.
// ===========================================================================
__global__ void __launch_bounds__(128, 4) main_kernel(
    const float* __restrict__ invf, const float* __restrict__ evf,
    const float* __restrict__ fi_w1, const float* __restrict__ fi_b1,
    const float* __restrict__ fi_b2,
    const float* __restrict__ fe_w1, const float* __restrict__ fe_b1,
    const float* __restrict__ fe_b2,
    const float* __restrict__ w_int, const float* __restrict__ b_int,
    float* __restrict__ out1, float* __restrict__ out2,
    float* __restrict__ fwi, float* __restrict__ fwe,
    int N, int E, int NB)
{
    int bid = blockIdx.x;
    int tid = threadIdx.x;
    int warp = tid >> 5, lane = tid & 31;

    if (bid >= NB) {
        // =============== EDGE PATH =========================================
        __shared__ __align__(16) float s_e1[32][24];   // [k][edge], stride 24
        __shared__ __align__(16) float4 s_inv[16];
        __shared__ float s_tf[16];
        __shared__ int   s_ti[16];
        __shared__ float s_bias[128];

        int eb = bid - NB;
        int filt = eb & 1;
        int ebid = eb >> 1;
        const float* we1 = filt ? fe_w1 : fi_w1;
        const float* be1 = filt ? fe_b1 : fi_b1;
        const float* be2 = filt ? fe_b2 : fi_b2;
        float* outp = filt ? fwe : fwi;
        const __half* tab = g_htabh[filt];

        s_bias[tid] = __ldg(be2 + tid);

        int tg = lane >> 2;     // 0..7
        int tq = lane & 3;      // 0..3
        int k1 = tid & 31;      // layer-1 hidden index for this thread
        float w1l0 = __ldg(we1 + k1),      w1l1 = __ldg(we1 + 32 + k1);
        float w1l2 = __ldg(we1 + 64 + k1), w1l3 = __ldg(we1 + 96 + k1);
        float blv  = __ldg(be1 + k1);

        // hi-weight fragments in registers: warp owns cols [warp*32, warp*32+32)
        float2 wh[4][4];        // [nt][ks]
#pragma unroll
        for (int nt = 0; nt < 4; nt++)
#pragma unroll
            for (int ks = 0; ks < 4; ks++) {
                const float2* src = reinterpret_cast<const float2*>(g_wpk[filt][0] + ks * 1024);
                wh[nt][ks] = __ldg(src + ((warp * 4 + nt) * 8 + tg) * 4 + tq);
            }
        __syncthreads();

        for (int base = ebid * 16; base < E; base += EB * 16) {
            // ---- stage 16 edges ----
            if (tid < 16) {
                int e = base + tid; if (e >= E) e = E - 1;
                s_inv[tid] = g_einv[e];
                float2 m = g_etf[e];
                s_tf[tid] = m.x;
                s_ti[tid] = __float_as_int(m.y);
            }
            __syncthreads();

            // ---- layer 1: thread = (k, 4 edges) ----
            {
                int e0 = warp * 4;
                float a0, a1, a2, a3;
                {
                    float4 v = s_inv[e0];
                    a0 = silu_f(fmaf(v.x, w1l0, fmaf(v.y, w1l1, fmaf(v.z, w1l2, fmaf(v.w, w1l3, blv)))));
                    v = s_inv[e0 + 1];
                    a1 = silu_f(fmaf(v.x, w1l0, fmaf(v.y, w1l1, fmaf(v.z, w1l2, fmaf(v.w, w1l3, blv)))));
                    v = s_inv[e0 + 2];
                    a2 = silu_f(fmaf(v.x, w1l0, fmaf(v.y, w1l1, fmaf(v.z, w1l2, fmaf(v.w, w1l3, blv)))));
                    v = s_inv[e0 + 3];
                    a3 = silu_f(fmaf(v.x, w1l0, fmaf(v.y, w1l1, fmaf(v.z, w1l2, fmaf(v.w, w1l3, blv)))));
                }
                *reinterpret_cast<float4*>(&s_e1[k1][warp * 4]) = make_float4(a0, a1, a2, a3);
            }
            __syncthreads();

            // ---- layer 2: tf32 MMA, warp covers 32 cols (4 n-tiles) ----
            float c[4][4];
#pragma unroll
            for (int nt = 0; nt < 4; nt++) {
                float bx = s_bias[(warp * 4 + nt) * 8 + tq * 2];
                float by = s_bias[(warp * 4 + nt) * 8 + tq * 2 + 1];
                c[nt][0] = bx; c[nt][1] = by; c[nt][2] = bx; c[nt][3] = by;
            }
#pragma unroll
            for (int ks = 0; ks < 4; ks++) {
                float f0 = s_e1[ks * 8 + tq][tg];
                float f1 = s_e1[ks * 8 + tq][tg + 8];
                float f2 = s_e1[ks * 8 + tq + 4][tg];
                float f3 = s_e1[ks * 8 + tq + 4][tg + 8];
                unsigned ah0 = tf32_rna(f0), ah1 = tf32_rna(f1);
                unsigned ah2 = tf32_rna(f2), ah3 = tf32_rna(f3);
                unsigned al0 = tf32_rna(f0 - __uint_as_float(ah0));
                unsigned al1 = tf32_rna(f1 - __uint_as_float(ah1));
                unsigned al2 = tf32_rna(f2 - __uint_as_float(ah2));
                unsigned al3 = tf32_rna(f3 - __uint_as_float(ah3));
                const float2* wlb = reinterpret_cast<const float2*>(g_wpk[filt][1] + ks * 1024);
#pragma unroll
                for (int nt = 0; nt < 4; nt++) {
                    float2 bh = wh[nt][ks];
                    float2 bo = __ldg(wlb + ((warp * 4 + nt) * 8 + tg) * 4 + tq);
                    unsigned bh0 = __float_as_uint(bh.x), bh1 = __float_as_uint(bh.y);
                    unsigned bl0 = __float_as_uint(bo.x), bl1 = __float_as_uint(bo.y);
                    mma_tf32(c[nt], ah0, ah1, ah2, ah3, bh0, bh1);
                    mma_tf32(c[nt], al0, al1, al2, al3, bh0, bh1);
                    mma_tf32(c[nt], ah0, ah1, ah2, ah3, bl0, bl1);
                }
            }

            // ---- epilogue: silu + fp16 table lerp + store ----
#pragma unroll
            for (int hh = 0; hh < 2; hh++) {
                int r = tg + hh * 8;
                int e = base + r;
                if (e < E) {
                    float tf = s_tf[r];
                    int   ti = s_ti[r];
                    const __half2* t0 = reinterpret_cast<const __half2*>(tab) + (size_t)ti * 64;
#pragma unroll
                    for (int nt = 0; nt < 4; nt++) {
                        int h2i = (warp * 4 + nt) * 4 + tq;
                        __half2 ha = __ldg(t0 + h2i);
                        __half2 hb = __ldg(t0 + 64 + h2i);
                        float2 fa = __half22float2(ha);
                        float2 fb = __half22float2(hb);
                        float cx = c[nt][hh * 2], cy = c[nt][hh * 2 + 1];
                        float2 o;
                        o.x = fmaf(tf, fb.x - fa.x, fa.x) + silu_f(cx);
                        o.y = fmaf(tf, fb.y - fa.y, fa.y) + silu_f(cy);
                        *reinterpret_cast<float2*>(outp + (size_t)e * 128
                            + (warp * 4 + nt) * 8 + tq * 2) = o;
                    }
                }
            }
            __syncthreads();
        }
        return;
    }

    // =============== NODE PATH ==============================================
    __shared__ float2 xs[4][4][136];
    int ngrp = (N + 7) >> 3;
    int grp = bid * 4 + warp;
    if (grp >= ngrp) return;
    int nbase = grp * 8;
    int o4 = (lane < 4) ? (128 + lane) : lane;

    float attv[8];
#pragma unroll
    for (int nd = 0; nd < 8; nd++) {
        int n = nbase + nd; if (n >= N) n = N - 1;
        float* Xp = reinterpret_cast<float*>(xs[warp][nd >> 1]) + (nd & 1);
#pragma unroll
        for (int j = 0; j < 4; j++)
            Xp[2 * (lane + 32 * j)] = 2.0f * __ldg(invf + (size_t)n * 128 + lane + 32 * j);
        float av = 0.f, dsq = 0.f;
        if (lane < 16) { av = 2.0f * __ldg(evf + (size_t)n * 16 + lane); dsq = av * av; }
        attv[nd] = av;
        float v0 = __shfl_sync(FULLMASK, dsq, 0);
        float v1 = __shfl_sync(FULLMASK, dsq, 1) + __shfl_sync(FULLMASK, dsq, 2)
                 + __shfl_sync(FULLMASK, dsq, 3);
        float v2 = __shfl_sync(FULLMASK, dsq, 4) + __shfl_sync(FULLMASK, dsq, 5)
                 + __shfl_sync(FULLMASK, dsq, 6) + __shfl_sync(FULLMASK, dsq, 7)
                 + __shfl_sync(FULLMASK, dsq, 8);
        float v3 = __shfl_sync(FULLMASK, dsq, 9) + __shfl_sync(FULLMASK, dsq, 10)
                 + __shfl_sync(FULLMASK, dsq, 11) + __shfl_sync(FULLMASK, dsq, 12)
                 + __shfl_sync(FULLMASK, dsq, 13) + __shfl_sync(FULLMASK, dsq, 14)
                 + __shfl_sync(FULLMASK, dsq, 15);
        if (lane == 0) { Xp[2*128] = v0; Xp[2*129] = v1; Xp[2*130] = v2; Xp[2*131] = v3; }
    }
    __syncwarp();

    ull acc[4][5];
    {
        ull d0 = dup2(__ldg(b_int + lane)),      d1 = dup2(__ldg(b_int + 32 + lane));
        ull d2 = dup2(__ldg(b_int + 64 + lane)), d3 = dup2(__ldg(b_int + 96 + lane));
        ull d4 = dup2(__ldg(b_int + o4));
#pragma unroll
        for (int p = 0; p < 4; p++) {
            acc[p][0] = d0; acc[p][1] = d1; acc[p][2] = d2; acc[p][3] = d3; acc[p][4] = d4;
        }
    }
#pragma unroll 2
    for (int i = 0; i < 132; i++) {
        const float* wr = w_int + i * 132;
        ull w0 = dup2(__ldg(wr + lane)),      w1 = dup2(__ldg(wr + 32 + lane));
        ull w2 = dup2(__ldg(wr + 64 + lane)), w3 = dup2(__ldg(wr + 96 + lane));
        ull w4 = dup2(__ldg(wr + o4));
#pragma unroll
        for (int p = 0; p < 4; p++) {
            ull x = reinterpret_cast<const ull*>(xs[warp][p])[i];
            fma2(acc[p][0], w0, x); fma2(acc[p][1], w1, x);
            fma2(acc[p][2], w2, x); fma2(acc[p][3], w3, x);
            fma2(acc[p][4], w4, x);
        }
    }
#pragma unroll
    for (int nd = 0; nd < 8; nd++) {
        int n = nbase + nd;
        if (n >= N) break;
        int p = nd >> 1, s = nd & 1;
        const float* Xp = reinterpret_cast<const float*>(xs[warp][p]) + s;
        float lo, hi, a0, a1, a2, a3, a4;
        unpack2(acc[p][0], lo, hi); a0 = s ? hi : lo;
        unpack2(acc[p][1], lo, hi); a1 = s ? hi : lo;
        unpack2(acc[p][2], lo, hi); a2 = s ? hi : lo;
        unpack2(acc[p][3], lo, hi); a3 = s ? hi : lo;
        unpack2(acc[p][4], lo, hi); a4 = s ? hi : lo;
        out1[(size_t)n * 128 + lane]      = Xp[2 * (lane)]      + a0;
        out1[(size_t)n * 128 + 32 + lane] = Xp[2 * (32 + lane)] + a1;
        out1[(size_t)n * 128 + 64 + lane] = Xp[2 * (64 + lane)] + a2;
        out1[(size_t)n * 128 + 96 + lane] = Xp[2 * (96 + lane)] + a3;
        float c0 = __shfl_sync(FULLMASK, a4, 0), c1 = __shfl_sync(FULLMASK, a4, 1);
        float c2 = __shfl_sync(FULLMASK, a4, 2), c3 = __shfl_sync(FULLMASK, a4, 3);
        if (lane < 16) {
            float bs = (lane == 0) ? c0 : ((lane < 4) ? c1 : ((lane < 9) ? c2 : c3));
            out2[(size_t)n * 16 + lane] = attv[nd] * (1.0f + bs);
        }
    }
}

// ---------------------------------------------------------------------------
extern "C" void kernel_launch(void* const* d_in, const int* in_sizes, int n_in,
                              void* d_out, int out_size)
{
    const float* invf      = (const float*)d_in[0];
    const float* evf       = (const float*)d_in[1];
    const int*   senders   = (const int*)  d_in[2];
    const int*   receivers = (const int*)  d_in[3];
    const float* lengths   = (const float*)d_in[5];
    const float* fi_rbf_w1 = (const float*)d_in[7];
    const float* fi_rbf_b1 = (const float*)d_in[8];
    const float* fi_rbf_w2 = (const float*)d_in[9];
    const float* fi_rbf_b2 = (const float*)d_in[10];
    const float* fi_ev_w1  = (const float*)d_in[11];
    const float* fi_ev_b1  = (const float*)d_in[12];
    const float* fi_ev_w2  = (const float*)d_in[13];
    const float* fi_ev_b2  = (const float*)d_in[14];
    const float* fe_rbf_w1 = (const float*)d_in[15];
    const float* fe_rbf_b1 = (const float*)d_in[16];
    const float* fe_rbf_w2 = (const float*)d_in[17];
    const float* fe_rbf_b2 = (const float*)d_in[18];
    const float* fe_ev_w1  = (const float*)d_in[19];
    const float* fe_ev_b1  = (const float*)d_in[20];
    const float* fe_ev_w2  = (const float*)d_in[21];
    const float* fe_ev_b2  = (const float*)d_in[22];
    const float* w_int     = (const float*)d_in[23];
    const float* b_int     = (const float*)d_in[24];

    int N = in_sizes[0] / 128;
    int E = in_sizes[5];

    float* out1 = (float*)d_out;
    float* out2 = out1 + (size_t)N * 128;
    float* fwi  = out2 + (size_t)N * 16;
    float* fwe  = fwi  + (size_t)E * 128;

    int PB = (E + 255) / 256;
    int ngrp = (N + 7) / 8;
    int NB = (ngrp + 3) / 4;

    setup_kernel<<<144 + PB, 256>>>(
        evf, senders, receivers, lengths,
        fi_rbf_w1, fi_rbf_b1, fi_rbf_w2, fi_rbf_b2,
        fe_rbf_w1, fe_rbf_b1, fe_rbf_w2, fe_rbf_b2,
        fi_ev_w2, fe_ev_w2, E);

    main_kernel<<<NB + 2 * EB, 128>>>(
        invf, evf,
        fi_ev_w1, fi_ev_b1, fi_ev_b2,
        fe_ev_w1, fe_ev_b1, fe_ev_b2,
        w_int, b_int, out1, out2, fwi, fwe, N, E, NB);
}

// round 14
// speedup vs baseline: 1.2146x; 1.2146x over previous
#include <cuda_runtime.h>
#include <cuda_fp16.h>

#define TAB 2048
#define FULLMASK 0xffffffffu
#define EBF 1184           // edge blocks per filter
typedef unsigned long long ull;

__device__ __half g_htabh[2][TAB * 128];   // fp16 length->h tables
__device__ float4 g_einv[1000000];         // per-edge SO3 invariants
__device__ float2 g_etf[1000000];          // per-edge (tf, bitcast ti)

__device__ __forceinline__ float silu_f(float x) {
    float h = 0.5f * x, t;
    asm("tanh.approx.f32 %0, %1;" : "=f"(t) : "f"(h));
    return fmaf(h, t, h);
}
__device__ __forceinline__ float silu_acc(float x) { return __fdividef(x, 1.0f + __expf(-x)); }

__device__ __forceinline__ ull dup2(float x) {
    ull r; unsigned u = __float_as_uint(x);
    asm("mov.b64 %0, {%1,%1};" : "=l"(r) : "r"(u)); return r;
}
__device__ __forceinline__ ull pack2(float a, float b) {
    ull r;
    asm("mov.b64 %0, {%1,%2};" : "=l"(r) : "r"(__float_as_uint(a)), "r"(__float_as_uint(b)));
    return r;
}
__device__ __forceinline__ void fma2(ull &d, ull a, ull b) {
    asm("fma.rn.f32x2 %0, %1, %2, %0;" : "+l"(d) : "l"(a), "l"(b));
}
__device__ __forceinline__ void unpack2(ull v, float &lo, float &hi) {
    unsigned a, b; asm("mov.b64 {%0,%1}, %2;" : "=r"(a), "=r"(b) : "l"(v));
    lo = __uint_as_float(a); hi = __uint_as_float(b);
}

// ===========================================================================
// Setup kernel: [0,128) fp16 table build (w2 via __ldg, L1-resident),
//               [128,128+PB) per-edge prep
// ===========================================================================
__global__ void __launch_bounds__(256) setup_kernel(
    const float* __restrict__ evf,
    const int* __restrict__ senders, const int* __restrict__ receivers,
    const float* __restrict__ lengths,
    const float* __restrict__ fi_rbf_w1, const float* __restrict__ fi_rbf_b1,
    const float* __restrict__ fi_rbf_w2, const float* __restrict__ fi_rbf_b2,
    const float* __restrict__ fe_rbf_w1, const float* __restrict__ fe_rbf_b1,
    const float* __restrict__ fe_rbf_w2, const float* __restrict__ fe_rbf_b2,
    int E)
{
    int bid = blockIdx.x;
    int tid = threadIdx.x;

    if (bid < 128) {
        // ---- table build: 64 blocks per filter, 32 rows/block ----
        int filt = bid >> 6;
        const float* w1 = filt ? fe_rbf_w1 : fi_rbf_w1;
        const float* b1 = filt ? fe_rbf_b1 : fi_rbf_b1;
        const float* w2 = filt ? fe_rbf_w2 : fi_rbf_w2;
        const float* b2 = filt ? fe_rbf_b2 : fi_rbf_b2;
        __shared__ float h1s[128];
        int f = tid & 127;
        float w1col[32];
#pragma unroll
        for (int k = 0; k < 32; k++) w1col[k] = __ldg(&w1[k * 128 + f]);
        float b1f = __ldg(&b1[f]), b2f = __ldg(&b2[f]);
        const float step  = 5.0f / 31.0f;
        const float gamma = 0.5f / (step * step);
        const float dx    = 5.0f / (float)(TAB - 1);
        int r0 = (bid & 63) * 32;
        for (int rr = 0; rr < 32; rr++) {
            int row = r0 + rr;
            float x = (float)row * dx;
            float a1 = b1f;
#pragma unroll
            for (int k = 0; k < 32; k++) {
                float d = x - (float)k * step;
                a1 = fmaf(__expf(-gamma * d * d), w1col[k], a1);
            }
            if (tid < 128) h1s[f] = silu_acc(a1);
            __syncthreads();
            float a2 = b2f;
#pragma unroll 16
            for (int k = 0; k < 128; k++) a2 = fmaf(h1s[k], __ldg(&w2[k * 128 + f]), a2);
            if (tid < 128)
                g_htabh[filt][(size_t)row * 128 + f] = __float2half_rn(silu_acc(a2));
            __syncthreads();
        }
        return;
    }

    // ---- edge prep: one edge per thread ----
    int e = (bid - 128) * 256 + tid;
    if (e >= E) return;
    const float tscale = (float)(TAB - 1) / 5.0f;
    int sN = __ldg(senders + e), rN = __ldg(receivers + e);
    const float4* As = reinterpret_cast<const float4*>(evf) + (size_t)sN * 4;
    const float4* Ar = reinterpret_cast<const float4*>(evf) + (size_t)rN * 4;
    float4 a, b; float dx, dy, dz, dw;
    float i0, i1, i2, i3;
    a = __ldg(As);     b = __ldg(Ar);     dx = a.x-b.x; dy = a.y-b.y; dz = a.z-b.z; dw = a.w-b.w;
    i0 = dx*dx; i1 = dy*dy + dz*dz + dw*dw;
    a = __ldg(As + 1); b = __ldg(Ar + 1); dx = a.x-b.x; dy = a.y-b.y; dz = a.z-b.z; dw = a.w-b.w;
    i2 = dx*dx + dy*dy + dz*dz + dw*dw;
    a = __ldg(As + 2); b = __ldg(Ar + 2); dx = a.x-b.x; dy = a.y-b.y; dz = a.z-b.z; dw = a.w-b.w;
    i2 += dx*dx; i3 = dy*dy + dz*dz + dw*dw;
    a = __ldg(As + 3); b = __ldg(Ar + 3); dx = a.x-b.x; dy = a.y-b.y; dz = a.z-b.z; dw = a.w-b.w;
    i3 += dx*dx + dy*dy + dz*dz + dw*dw;
    float xf = __ldg(lengths + e) * tscale;
    int ti = (int)xf;
    if (ti < 0) ti = 0; if (ti > TAB - 2) ti = TAB - 2;
    g_einv[e] = make_float4(i0, i1, i2, i3);
    g_etf[e]  = make_float2(xf - (float)ti, __int_as_float(ti));
}

// ===========================================================================
// Main kernel (256 threads, 3 blocks/SM):
//   blocks [0, 2*EBF)  : edge filter nets (filt = bid&1) — R8-proven f32x2 path
//   blocks [2*EBF, +NB): node update (LSU-bound; overlaps edge fma work)
// Shared memory overlaid between the two paths.
// ===========================================================================
__global__ void __launch_bounds__(256, 3) main_kernel(
    const float* __restrict__ invf, const float* __restrict__ evf,
    const float* __restrict__ fi_w1, const float* __restrict__ fi_b1,
    const float* __restrict__ fi_w2, const float* __restrict__ fi_b2,
    const float* __restrict__ fe_w1, const float* __restrict__ fe_b1,
    const float* __restrict__ fe_w2, const float* __restrict__ fe_b2,
    const float* __restrict__ w_int, const float* __restrict__ b_int,
    float* __restrict__ out1, float* __restrict__ out2,
    float* __restrict__ fwi, float* __restrict__ fwe,
    int N, int E)
{
    __shared__ __align__(16) char smbuf[34816];
    int bid = blockIdx.x;
    int tid = threadIdx.x;
    int warp = tid >> 5, lane = tid & 31;

    if (bid < 2 * EBF) {
        // =============== EDGE PATH (R8 layout) =============================
        float*  s_we2 = reinterpret_cast<float*>(smbuf);                    // 16384 B
        float2* s_e1  = reinterpret_cast<float2*>(smbuf + 16384);           // 8192 B
        float4* s_edv = reinterpret_cast<float4*>(smbuf + 24576);           // 1024 B
        float2* s_m   = reinterpret_cast<float2*>(smbuf + 25600);           // 512 B

        int filt = bid & 1;
        int ebid = bid >> 1;
        const float* we1 = filt ? fe_w1 : fi_w1; const float* be1 = filt ? fe_b1 : fi_b1;
        const float* we2 = filt ? fe_w2 : fi_w2; const float* be2 = filt ? fe_b2 : fi_b2;
        float* outp = filt ? fwe : fwi;
        const __half* tabh = g_htabh[filt];

        for (int i = tid; i < 4096; i += 256) s_we2[i] = __ldg(we2 + i);
        __syncthreads();

        float w1l0 = __ldg(we1 + lane),      w1l1 = __ldg(we1 + 32 + lane);
        float w1l2 = __ldg(we1 + 64 + lane), w1l3 = __ldg(we1 + 96 + lane);
        float bl   = __ldg(be1 + lane);
        float4 bb  = __ldg(reinterpret_cast<const float4*>(be2) + lane);
        ull bd0 = dup2(bb.x), bd1 = dup2(bb.y), bd2 = dup2(bb.z), bd3 = dup2(bb.w);
        const float4* wv = reinterpret_cast<const float4*>(s_we2);
        float4* outv = reinterpret_cast<float4*>(outp);

        int gw = ebid * 8 + warp;
        int nwarps = EBF * 8;

        for (int base = gw * 8; base < E; base += nwarps * 8) {
            if (lane < 8) {
                int e = base + lane; if (e >= E) e = E - 1;
                s_edv[warp * 8 + lane] = g_einv[e];
                s_m[warp * 8 + lane]   = g_etf[e];
            }
            __syncwarp();

            // layer 1: hidden = lane, edge pairs into float2
#pragma unroll
            for (int p = 0; p < 4; p++) {
                float4 v0 = s_edv[warp * 8 + 2 * p];
                float4 v1 = s_edv[warp * 8 + 2 * p + 1];
                float ea = silu_f(fmaf(v0.x, w1l0, fmaf(v0.y, w1l1,
                                  fmaf(v0.z, w1l2, fmaf(v0.w, w1l3, bl)))));
                float eb = silu_f(fmaf(v1.x, w1l0, fmaf(v1.y, w1l1,
                                  fmaf(v1.z, w1l2, fmaf(v1.w, w1l3, bl)))));
                s_e1[(warp * 4 + p) * 32 + lane] = make_float2(ea, eb);
            }
            __syncwarp();

            // layer 2: 32 -> 128, f32x2 over edge pairs
            ull acc[4][4];
#pragma unroll
            for (int p = 0; p < 4; p++) { acc[p][0] = bd0; acc[p][1] = bd1; acc[p][2] = bd2; acc[p][3] = bd3; }
            const float4* e1v = reinterpret_cast<const float4*>(s_e1 + warp * 128);
#pragma unroll 2
            for (int k2 = 0; k2 < 16; k2++) {
                float4 wa = wv[(2 * k2) * 32 + lane];
                float4 wb = wv[(2 * k2 + 1) * 32 + lane];
                ull wa0 = dup2(wa.x), wa1 = dup2(wa.y), wa2 = dup2(wa.z), wa3 = dup2(wa.w);
                ull wb0 = dup2(wb.x), wb1 = dup2(wb.y), wb2 = dup2(wb.z), wb3 = dup2(wb.w);
#pragma unroll
                for (int p = 0; p < 4; p++) {
                    float4 cc = e1v[p * 16 + k2];
                    ull c0 = pack2(cc.x, cc.y);
                    ull c1 = pack2(cc.z, cc.w);
                    fma2(acc[p][0], wa0, c0); fma2(acc[p][1], wa1, c0);
                    fma2(acc[p][2], wa2, c0); fma2(acc[p][3], wa3, c0);
                    fma2(acc[p][0], wb0, c1); fma2(acc[p][1], wb1, c1);
                    fma2(acc[p][2], wb2, c1); fma2(acc[p][3], wb3, c1);
                }
            }

            // epilogue: silu + fp16 table lerp + store
#pragma unroll
            for (int p = 0; p < 4; p++) {
                float l0, h0, l1, h1, l2, h2, l3, h3;
                unpack2(acc[p][0], l0, h0); unpack2(acc[p][1], l1, h1);
                unpack2(acc[p][2], l2, h2); unpack2(acc[p][3], l3, h3);
#pragma unroll
                for (int hh = 0; hh < 2; hh++) {
                    int j = 2 * p + hh;
                    int e = base + j;
                    if (e < E) {
                        float e0 = hh ? h0 : l0, e1 = hh ? h1 : l1;
                        float e2 = hh ? h2 : l2, e3 = hh ? h3 : l3;
                        float tf = s_m[warp * 8 + j].x;
                        int   ti = __float_as_int(s_m[warp * 8 + j].y);
                        const uint2* ta = reinterpret_cast<const uint2*>(tabh + (size_t)ti * 128) + lane;
                        uint2 ua = __ldg(ta);
                        uint2 ub = __ldg(ta + 32);
                        float2 a01 = __half22float2(*reinterpret_cast<__half2*>(&ua.x));
                        float2 a23 = __half22float2(*reinterpret_cast<__half2*>(&ua.y));
                        float2 b01 = __half22float2(*reinterpret_cast<__half2*>(&ub.x));
                        float2 b23 = __half22float2(*reinterpret_cast<__half2*>(&ub.y));
                        float4 o;
                        o.x = fmaf(tf, b01.x - a01.x, a01.x) + silu_f(e0);
                        o.y = fmaf(tf, b01.y - a01.y, a01.y) + silu_f(e1);
                        o.z = fmaf(tf, b23.x - a23.x, a23.x) + silu_f(e2);
                        o.w = fmaf(tf, b23.y - a23.y, a23.y) + silu_f(e3);
                        outv[(size_t)e * 32 + lane] = o;
                    }
                }
            }
            __syncwarp();
        }
        return;
    }

    // =============== NODE PATH (R8 layout, 8 nodes/warp) ====================
    float2* xs = reinterpret_cast<float2*>(smbuf);      // [8 warps][4 pairs][136]
    int ngrp = (N + 7) >> 3;
    int grp = (bid - 2 * EBF) * 8 + warp;
    if (grp >= ngrp) return;
    int nbase = grp * 8;
    int o4 = (lane < 4) ? (128 + lane) : lane;
    float2* xw = xs + warp * 4 * 136;

    float attv[8];
#pragma unroll
    for (int nd = 0; nd < 8; nd++) {
        int n = nbase + nd; if (n >= N) n = N - 1;
        float* Xp = reinterpret_cast<float*>(xw + (nd >> 1) * 136) + (nd & 1);
#pragma unroll
        for (int j = 0; j < 4; j++)
            Xp[2 * (lane + 32 * j)] = 2.0f * __ldg(invf + (size_t)n * 128 + lane + 32 * j);
        float av = 0.f, dsq = 0.f;
        if (lane < 16) { av = 2.0f * __ldg(evf + (size_t)n * 16 + lane); dsq = av * av; }
        attv[nd] = av;
        float v0 = __shfl_sync(FULLMASK, dsq, 0);
        float v1 = __shfl_sync(FULLMASK, dsq, 1) + __shfl_sync(FULLMASK, dsq, 2)
                 + __shfl_sync(FULLMASK, dsq, 3);
        float v2 = __shfl_sync(FULLMASK, dsq, 4) + __shfl_sync(FULLMASK, dsq, 5)
                 + __shfl_sync(FULLMASK, dsq, 6) + __shfl_sync(FULLMASK, dsq, 7)
                 + __shfl_sync(FULLMASK, dsq, 8);
        float v3 = __shfl_sync(FULLMASK, dsq, 9) + __shfl_sync(FULLMASK, dsq, 10)
                 + __shfl_sync(FULLMASK, dsq, 11) + __shfl_sync(FULLMASK, dsq, 12)
                 + __shfl_sync(FULLMASK, dsq, 13) + __shfl_sync(FULLMASK, dsq, 14)
                 + __shfl_sync(FULLMASK, dsq, 15);
        if (lane == 0) { Xp[2*128] = v0; Xp[2*129] = v1; Xp[2*130] = v2; Xp[2*131] = v3; }
    }
    __syncwarp();

    ull acc[4][5];
    {
        ull d0 = dup2(__ldg(b_int + lane)),      d1 = dup2(__ldg(b_int + 32 + lane));
        ull d2 = dup2(__ldg(b_int + 64 + lane)), d3 = dup2(__ldg(b_int + 96 + lane));
        ull d4 = dup2(__ldg(b_int + o4));
#pragma unroll
        for (int p = 0; p < 4; p++) {
            acc[p][0] = d0; acc[p][1] = d1; acc[p][2] = d2; acc[p][3] = d3; acc[p][4] = d4;
        }
    }
#pragma unroll 2
    for (int i = 0; i < 132; i++) {
        const float* wr = w_int + i * 132;
        ull w0 = dup2(__ldg(wr + lane)),      ww1 = dup2(__ldg(wr + 32 + lane));
        ull w2 = dup2(__ldg(wr + 64 + lane)), w3 = dup2(__ldg(wr + 96 + lane));
        ull w4 = dup2(__ldg(wr + o4));
#pragma unroll
        for (int p = 0; p < 4; p++) {
            ull x = reinterpret_cast<const ull*>(xw + p * 136)[i];
            fma2(acc[p][0], w0, x); fma2(acc[p][1], ww1, x);
            fma2(acc[p][2], w2, x); fma2(acc[p][3], w3, x);
            fma2(acc[p][4], w4, x);
        }
    }
#pragma unroll
    for (int nd = 0; nd < 8; nd++) {
        int n = nbase + nd;
        if (n >= N) break;
        int p = nd >> 1, s = nd & 1;
        const float* Xp = reinterpret_cast<const float*>(xw + p * 136) + s;
        float lo, hi, a0, a1, a2, a3, a4;
        unpack2(acc[p][0], lo, hi); a0 = s ? hi : lo;
        unpack2(acc[p][1], lo, hi); a1 = s ? hi : lo;
        unpack2(acc[p][2], lo, hi); a2 = s ? hi : lo;
        unpack2(acc[p][3], lo, hi); a3 = s ? hi : lo;
        unpack2(acc[p][4], lo, hi); a4 = s ? hi : lo;
        out1[(size_t)n * 128 + lane]      = Xp[2 * (lane)]      + a0;
        out1[(size_t)n * 128 + 32 + lane] = Xp[2 * (32 + lane)] + a1;
        out1[(size_t)n * 128 + 64 + lane] = Xp[2 * (64 + lane)] + a2;
        out1[(size_t)n * 128 + 96 + lane] = Xp[2 * (96 + lane)] + a3;
        float c0 = __shfl_sync(FULLMASK, a4, 0), c1 = __shfl_sync(FULLMASK, a4, 1);
        float c2 = __shfl_sync(FULLMASK, a4, 2), c3 = __shfl_sync(FULLMASK, a4, 3);
        if (lane < 16) {
            float bs = (lane == 0) ? c0 : ((lane < 4) ? c1 : ((lane < 9) ? c2 : c3));
            out2[(size_t)n * 16 + lane] = attv[nd] * (1.0f + bs);
        }
    }
}

// ---------------------------------------------------------------------------
extern "C" void kernel_launch(void* const* d_in, const int* in_sizes, int n_in,
                              void* d_out, int out_size)
{
    const float* invf      = (const float*)d_in[0];
    const float* evf       = (const float*)d_in[1];
    const int*   senders   = (const int*)  d_in[2];
    const int*   receivers = (const int*)  d_in[3];
    const float* lengths   = (const float*)d_in[5];
    const float* fi_rbf_w1 = (const float*)d_in[7];
    const float* fi_rbf_b1 = (const float*)d_in[8];
    const float* fi_rbf_w2 = (const float*)d_in[9];
    const float* fi_rbf_b2 = (const float*)d_in[10];
    const float* fi_ev_w1  = (const float*)d_in[11];
    const float* fi_ev_b1  = (const float*)d_in[12];
    const float* fi_ev_w2  = (const float*)d_in[13];
    const float* fi_ev_b2  = (const float*)d_in[14];
    const float* fe_rbf_w1 = (const float*)d_in[15];
    const float* fe_rbf_b1 = (const float*)d_in[16];
    const float* fe_rbf_w2 = (const float*)d_in[17];
    const float* fe_rbf_b2 = (const float*)d_in[18];
    const float* fe_ev_w1  = (const float*)d_in[19];
    const float* fe_ev_b1  = (const float*)d_in[20];
    const float* fe_ev_w2  = (const float*)d_in[21];
    const float* fe_ev_b2  = (const float*)d_in[22];
    const float* w_int     = (const float*)d_in[23];
    const float* b_int     = (const float*)d_in[24];

    int N = in_sizes[0] / 128;
    int E = in_sizes[5];

    float* out1 = (float*)d_out;
    float* out2 = out1 + (size_t)N * 128;
    float* fwi  = out2 + (size_t)N * 16;
    float* fwe  = fwi  + (size_t)E * 128;

    int PB = (E + 255) / 256;
    int ngrp = (N + 7) / 8;
    int NB = (ngrp + 7) / 8;

    setup_kernel<<<128 + PB, 256>>>(
        evf, senders, receivers, lengths,
        fi_rbf_w1, fi_rbf_b1, fi_rbf_w2, fi_rbf_b2,
        fe_rbf_w1, fe_rbf_b1, fe_rbf_w2, fe_rbf_b2, E);

    main_kernel<<<2 * EBF + NB, 256>>>(
        invf, evf,
        fi_ev_w1, fi_ev_b1, fi_ev_w2, fi_ev_b2,
        fe_ev_w1, fe_ev_b1, fe_ev_w2, fe_ev_b2,
        w_int, b_int, out1, out2, fwi, fwe, N, E);
}